// round 2
// baseline (speedup 1.0000x reference)
#include <cuda_runtime.h>

// DynamicModel: 2-step vehicle dynamics integrator.
// R2: smem weights (LDS.128), fast atan2 poly, split accumulators,
//     direct stores, occupancy 4 blocks/SM.

#define TPB   256
#define ROWS  8

#define LFc   1.5f
#define LRc   1.4f
#define CM1c  550.0f
#define CM2c  650.0f
#define DTc   0.01f
#define GRAVc 9.8f
#define MIZc  (1265.0f / 2000.0f)
#define CDRV  ((float)(3.45 * 0.919 / (0.34 * 1265.0)))

// A&S 4.4.49: atan(t), t in [0,1], abs err <= 1e-5
__device__ __forceinline__ float fast_atan2(float y, float x) {
    float ax = fabsf(x), ay = fabsf(y);
    float mx = fmaxf(ax, ay);
    float mn = fminf(ax, ay);
    float t  = __fdividef(mn, fmaxf(mx, 1e-30f));
    float t2 = t * t;
    float r  = 0.0208351f;
    r = fmaf(r, t2, -0.0851330f);
    r = fmaf(r, t2,  0.1801410f);
    r = fmaf(r, t2, -0.3302995f);
    r = fmaf(r, t2,  0.9998660f);
    float z = r * t;
    if (ay > ax)  z = 1.57079632679f - z;
    if (x < 0.0f) z = 3.14159265359f - z;
    return copysignf(z, y);
}

// 12-wide scalar MLP, weights from shared memory as float4, 4 partial sums.
__device__ __forceinline__ float mlp12s(float a,
                                        const float4* __restrict__ w1,
                                        const float4* __restrict__ b1,
                                        const float4* __restrict__ w2,
                                        float b2) {
    float s0 = b2, s1 = 0.0f, s2 = 0.0f, s3 = 0.0f;
#pragma unroll
    for (int g = 0; g < 3; g++) {
        float4 wv = w1[g];
        float4 bv = b1[g];
        float4 vv = w2[g];
        float h;
        h = fmaxf(fmaf(a, wv.x, bv.x), 0.0f); s0 = fmaf(h, vv.x, s0);
        h = fmaxf(fmaf(a, wv.y, bv.y), 0.0f); s1 = fmaf(h, vv.y, s1);
        h = fmaxf(fmaf(a, wv.z, bv.z), 0.0f); s2 = fmaf(h, vv.z, s2);
        h = fmaxf(fmaf(a, wv.w, bv.w), 0.0f); s3 = fmaf(h, vv.w, s3);
    }
    return (s0 + s1) + (s2 + s3);
}

__global__ __launch_bounds__(TPB, 4)
void dyn_kernel(const float4* __restrict__ x4,
                const float* __restrict__ fy_w1, const float* __restrict__ fy_b1,
                const float* __restrict__ fy_w2, const float* __restrict__ fy_b2,
                const float* __restrict__ ry_w1, const float* __restrict__ ry_b1,
                const float* __restrict__ ry_w2, const float* __restrict__ ry_b2,
                const float* __restrict__ rx_w, const float* __restrict__ rx_b,
                float* __restrict__ out, int B) {
    __shared__ __align__(16) float sw[80];

    const int t = threadIdx.x;
    // Cooperative one-shot weight gather into shared.
    if (t < 12)        sw[t]      = fy_w1[t];
    else if (t < 24)   sw[t]      = fy_b1[t - 12];
    else if (t < 36)   sw[t]      = fy_w2[t - 24];
    else if (t < 48)   sw[t]      = ry_w1[t - 36];
    else if (t < 60)   sw[t]      = ry_b1[t - 48];
    else if (t < 72)   sw[t]      = ry_w2[t - 60];
    else if (t == 72)  sw[72]     = *fy_b2;
    else if (t == 73)  sw[73]     = *ry_b2;
    else if (t == 74)  sw[74]     = *rx_w;
    else if (t == 75)  sw[75]     = *rx_b;
    __syncthreads();

    const float4* w1f = (const float4*)(sw + 0);
    const float4* b1f = (const float4*)(sw + 12);
    const float4* w2f = (const float4*)(sw + 24);
    const float4* w1r = (const float4*)(sw + 36);
    const float4* b1r = (const float4*)(sw + 48);
    const float4* w2r = (const float4*)(sw + 60);
    const float b2f = sw[72];
    const float b2r = sw[73];
    const float rxw = sw[74];
    const float rxb = sw[75];

    int i = blockIdx.x * (TPB * ROWS) + t;

    float4 a, b;
    if (i < B) { a = __ldg(x4 + 2 * i); b = __ldg(x4 + 2 * i + 1); }

#pragma unroll 1
    for (int r = 0; r < ROWS; r++) {
        const int inext = i + TPB;
        float4 an = a, bn = b;
        if (r + 1 < ROWS && inext < B) {          // prefetch next row
            an = __ldg(x4 + 2 * inext);
            bn = __ldg(x4 + 2 * inext + 1);
        }

        if (i < B) {
            const float pwm = a.x, theta = a.z, vx0 = a.w;
            const float vy0 = b.x, w0 = b.y, pitch = b.w;

            float st, ct;
            __sincosf(theta, &st, &ct);
            const float sp = __sinf(pitch);

            const float a_pred = (pwm > 0.0f ? CM1c : CM2c) * pwm * CDRV;
            const float vx_base = a_pred + rxb - GRAVc * sp;

            float o0 = 0.0f, o1 = 0.0f, o2 = 0.0f;
#pragma unroll
            for (int it = 0; it < 2; it++) {
                const float vx = vx0 + o0;
                const float vy = vy0 + o1;
                const float w  = w0  + o2;

                const float af = theta - fast_atan2(fmaf(w, LFc, vy), vx);
                const float ar = fast_atan2(fmaf(w, LRc, -vy), vx);

                float f = mlp12s(fabsf(af), w1f, b1f, w2f, b2f);
                const float Ffy = (af > 0.0f) ? f : -f;
                float g = mlp12s(fabsf(ar), w1r, b1r, w2r, b2r);
                const float Fry = (ar > 0.0f) ? g : -g;

                const float vx_dot = fmaf(rxw * vx, vx, vx_base) - Ffy * st + vy * w;
                const float vy_dot = fmaf(Ffy, ct, Fry) - vx * w;
                const float w_dot  = (Ffy * (LFc * ct) - Fry * LRc) * MIZc;

                o0 = fmaf(DTc, vx_dot, o0);
                o1 = fmaf(DTc, vy_dot, o1);
                o2 = fmaf(DTc, w_dot,  o2);
            }

            // direct stores: warp writes 384 contiguous bytes
            const int o = 3 * i;
            out[o + 0] = o0;
            out[o + 1] = o1;
            out[o + 2] = o2;
        }

        a = an; b = bn; i = inext;
    }
}

extern "C" void kernel_launch(void* const* d_in, const int* in_sizes, int n_in,
                              void* d_out, int out_size) {
    const float* x     = (const float*)d_in[0];
    const float* fy_w1 = (const float*)d_in[1];
    const float* fy_b1 = (const float*)d_in[2];
    const float* fy_w2 = (const float*)d_in[3];
    const float* fy_b2 = (const float*)d_in[4];
    const float* ry_w1 = (const float*)d_in[5];
    const float* ry_b1 = (const float*)d_in[6];
    const float* ry_w2 = (const float*)d_in[7];
    const float* ry_b2 = (const float*)d_in[8];
    const float* rx_w  = (const float*)d_in[9];
    const float* rx_b  = (const float*)d_in[10];
    float* out = (float*)d_out;

    const int B = in_sizes[0] / 8;
    const int rows_per_block = TPB * ROWS;
    const int grid = (B + rows_per_block - 1) / rows_per_block;

    dyn_kernel<<<grid, TPB>>>((const float4*)x,
                              fy_w1, fy_b1, fy_w2, fy_b2,
                              ry_w1, ry_b1, ry_w2, ry_b2,
                              rx_w, rx_b, out, B);
}

// round 3
// speedup vs baseline: 1.8057x; 1.8057x over previous
#include <cuda_runtime.h>

// DynamicModel: 2-step vehicle dynamics integrator.
// R3: MLPs evaluated as exact piecewise-linear functions (suffix-sum tables,
//     built per block with runtime validity check + exact fallback),
//     fast atan2 poly, register-light body for high occupancy.

#define TPB   256
#define ROWS  8

#define LFc   1.5f
#define LRc   1.4f
#define CM1c  550.0f
#define CM2c  650.0f
#define DTc   0.01f
#define GRAVc 9.8f
#define MIZc  (1265.0f / 2000.0f)
#define CDRV  ((float)(3.45 * 0.919 / (0.34 * 1265.0)))

// A&S 4.4.49 poly: abs err <= 1e-5 (validated R2: pipeline rel_err 5e-5)
__device__ __forceinline__ float fast_atan2(float y, float x) {
    float ax = fabsf(x), ay = fabsf(y);
    float mx = fmaxf(ax, ay);
    float mn = fminf(ax, ay);
    float t  = __fdividef(mn, fmaxf(mx, 1e-30f));
    float t2 = t * t;
    float r  = 0.0208351f;
    r = fmaf(r, t2, -0.0851330f);
    r = fmaf(r, t2,  0.1801410f);
    r = fmaf(r, t2, -0.3302995f);
    r = fmaf(r, t2,  0.9998660f);
    float z = r * t;
    if (ay > ax)  z = 1.57079632679f - z;
    if (x < 0.0f) z = 3.14159265359f - z;
    return copysignf(z, y);
}

// Fast path: piecewise-linear eval. a >= 0.
// c = c0 - a*s ; jmin = floor(c)+1 clamped [0,12] ; f = a*W[jmin] + B[jmin]
__device__ __forceinline__ float pwl_eval(float a, const float2* __restrict__ tab,
                                          float c0, float negs) {
    float c = fmaf(a, negs, c0);
    int jm = __float2int_rd(c) + 1;
    jm = min(12, max(jm, 0));
    float2 wb = tab[jm];
    return fmaf(a, wb.x, wb.y);
}

// Exact fallback: 12-unit MLP from smem raw weights [w1(12), b1(12), w2(12), b2]
__device__ __forceinline__ float mlp_slow(float a, const float* __restrict__ raw) {
    float s = raw[36];
#pragma unroll
    for (int j = 0; j < 12; j++) {
        float h = fmaxf(fmaf(a, raw[j], raw[12 + j]), 0.0f);
        s = fmaf(h, raw[24 + j], s);
    }
    return s;
}

struct SmemState {
    float tf[12], pwF[12], pbF[12];
    float tr[12], pwR[12], pbR[12];
    float2 tabF[13], tabR[13];
    float rawF[37], rawR[37];
    float rx[2];
    float scal[4];   // c0F, sF, c0R, sR
    int okF, okR;
};

template <bool FAST>
__device__ __forceinline__ void run_rows(
    const float4* __restrict__ x4, float* __restrict__ out, int B,
    int i, const SmemState* __restrict__ S,
    float rxw, float rxb,
    float c0F, float nsF, float c0R, float nsR)
{
    float4 a, b;
    if (i < B) { a = __ldg(x4 + 2 * i); b = __ldg(x4 + 2 * i + 1); }

#pragma unroll 1
    for (int r = 0; r < ROWS; r++) {
        const int inext = i + TPB;
        float4 an = a, bn = b;
        if (r + 1 < ROWS && inext < B) {
            an = __ldg(x4 + 2 * inext);
            bn = __ldg(x4 + 2 * inext + 1);
        }

        if (i < B) {
            const float pwm = a.x, theta = a.z, vx0 = a.w;
            const float vy0 = b.x, w0 = b.y, pitch = b.w;

            float st, ct;
            __sincosf(theta, &st, &ct);
            const float sp = __sinf(pitch);

            const float a_pred  = (pwm > 0.0f ? CM1c : CM2c) * pwm * CDRV;
            const float vx_base = a_pred + rxb - GRAVc * sp;
            const float lfct    = LFc * ct;   // hoisted

            float o0 = 0.0f, o1 = 0.0f, o2 = 0.0f;
#pragma unroll
            for (int it = 0; it < 2; it++) {
                const float vx = vx0 + o0;
                const float vy = vy0 + o1;
                const float w  = w0  + o2;

                const float af = theta - fast_atan2(fmaf(w, LFc, vy), vx);
                const float ar = fast_atan2(fmaf(w, LRc, -vy), vx);

                float f, g;
                if (FAST) {
                    f = pwl_eval(fabsf(af), S->tabF, c0F, nsF);
                    g = pwl_eval(fabsf(ar), S->tabR, c0R, nsR);
                } else {
                    f = mlp_slow(fabsf(af), S->rawF);
                    g = mlp_slow(fabsf(ar), S->rawR);
                }
                const float Ffy = (af > 0.0f) ? f : -f;
                const float Fry = (ar > 0.0f) ? g : -g;

                const float vx_dot = fmaf(rxw * vx, vx, vx_base) - Ffy * st + vy * w;
                const float vy_dot = fmaf(Ffy, ct, Fry) - vx * w;
                const float w_dot  = (Ffy * lfct - Fry * LRc) * MIZc;

                o0 = fmaf(DTc, vx_dot, o0);
                o1 = fmaf(DTc, vy_dot, o1);
                o2 = fmaf(DTc, w_dot,  o2);
            }

            const int o = 3 * i;
            out[o + 0] = o0;
            out[o + 1] = o1;
            out[o + 2] = o2;
        }
        a = an; b = bn; i = inext;
    }
}

__global__ __launch_bounds__(TPB)
void dyn_kernel(const float4* __restrict__ x4,
                const float* __restrict__ fy_w1, const float* __restrict__ fy_b1,
                const float* __restrict__ fy_w2, const float* __restrict__ fy_b2,
                const float* __restrict__ ry_w1, const float* __restrict__ ry_b1,
                const float* __restrict__ ry_w2, const float* __restrict__ ry_b2,
                const float* __restrict__ rx_w, const float* __restrict__ rx_b,
                float* __restrict__ out, int B) {
    __shared__ SmemState S;

    const int t = threadIdx.x;

    // ---- parallel per-unit prep ----
    if (t < 12) {
        float w1 = fy_w1[t], b1 = fy_b1[t], w2 = fy_w2[t];
        S.rawF[t] = w1; S.rawF[12 + t] = b1; S.rawF[24 + t] = w2;
        S.tf[t]  = -b1 / w1;
        S.pwF[t] = w2 * w1;
        S.pbF[t] = w2 * b1;
    } else if (t >= 32 && t < 44) {
        int j = t - 32;
        float w1 = ry_w1[j], b1 = ry_b1[j], w2 = ry_w2[j];
        S.rawR[j] = w1; S.rawR[12 + j] = b1; S.rawR[24 + j] = w2;
        S.tr[j]  = -b1 / w1;
        S.pwR[j] = w2 * w1;
        S.pbR[j] = w2 * b1;
    } else if (t == 64) {
        S.rawF[36] = *fy_b2;
        S.rawR[36] = *ry_b2;
        S.rx[0] = *rx_w;
        S.rx[1] = *rx_b;
    }
    __syncthreads();

    // ---- suffix sums + validity (one thread per net) ----
    if (t == 0) {
        float dt = S.tf[0] - S.tf[1];
        bool ok = (dt > 1e-9f);
#pragma unroll
        for (int j = 0; j < 12; j++) ok = ok && (S.rawF[j] > 0.0f);
#pragma unroll
        for (int j = 0; j < 11; j++)
            ok = ok && (fabsf((S.tf[j] - S.tf[j + 1]) - dt) <= 1e-4f * fabsf(dt) + 1e-7f);
        float W = 0.0f, Bc = S.rawF[36];
        S.tabF[12] = make_float2(0.0f, Bc);
        for (int jm = 11; jm >= 0; jm--) {
            W  += S.pwF[jm];
            Bc += S.pbF[jm];
            S.tabF[jm] = make_float2(W, Bc);
        }
        S.scal[0] = S.tf[0] / dt;
        S.scal[1] = 1.0f / dt;
        S.okF = ok ? 1 : 0;
    } else if (t == 32) {
        float dt = S.tr[0] - S.tr[1];
        bool ok = (dt > 1e-9f);
#pragma unroll
        for (int j = 0; j < 12; j++) ok = ok && (S.rawR[j] > 0.0f);
#pragma unroll
        for (int j = 0; j < 11; j++)
            ok = ok && (fabsf((S.tr[j] - S.tr[j + 1]) - dt) <= 1e-4f * fabsf(dt) + 1e-7f);
        float W = 0.0f, Bc = S.rawR[36];
        S.tabR[12] = make_float2(0.0f, Bc);
        for (int jm = 11; jm >= 0; jm--) {
            W  += S.pwR[jm];
            Bc += S.pbR[jm];
            S.tabR[jm] = make_float2(W, Bc);
        }
        S.scal[2] = S.tr[0] / dt;
        S.scal[3] = 1.0f / dt;
        S.okR = ok ? 1 : 0;
    }
    __syncthreads();

    const bool fast = (S.okF != 0) && (S.okR != 0);
    const float rxw = S.rx[0], rxb = S.rx[1];
    const float c0F = S.scal[0], nsF = -S.scal[1];
    const float c0R = S.scal[2], nsR = -S.scal[3];

    const int i0 = blockIdx.x * (TPB * ROWS) + t;

    if (fast)
        run_rows<true >(x4, out, B, i0, &S, rxw, rxb, c0F, nsF, c0R, nsR);
    else
        run_rows<false>(x4, out, B, i0, &S, rxw, rxb, c0F, nsF, c0R, nsR);
}

extern "C" void kernel_launch(void* const* d_in, const int* in_sizes, int n_in,
                              void* d_out, int out_size) {
    const float* x     = (const float*)d_in[0];
    const float* fy_w1 = (const float*)d_in[1];
    const float* fy_b1 = (const float*)d_in[2];
    const float* fy_w2 = (const float*)d_in[3];
    const float* fy_b2 = (const float*)d_in[4];
    const float* ry_w1 = (const float*)d_in[5];
    const float* ry_b1 = (const float*)d_in[6];
    const float* ry_w2 = (const float*)d_in[7];
    const float* ry_b2 = (const float*)d_in[8];
    const float* rx_w  = (const float*)d_in[9];
    const float* rx_b  = (const float*)d_in[10];
    float* out = (float*)d_out;

    const int B = in_sizes[0] / 8;
    const int rows_per_block = TPB * ROWS;
    const int grid = (B + rows_per_block - 1) / rows_per_block;

    dyn_kernel<<<grid, TPB>>>((const float4*)x,
                              fy_w1, fy_b1, fy_w2, fy_b2,
                              ry_w1, ry_b1, ry_w2, ry_b2,
                              rx_w, rx_b, out, B);
}